// round 4
// baseline (speedup 1.0000x reference)
#include <cuda_runtime.h>
#include <cuda_fp16.h>
#include <cstdint>

// ---------------------------------------------------------------------------
// Fused LSTM cell, B=262144, I=H=C=O=128, on sm_100 (compute_100 PTX target:
// no tcgen05). Uses warp-level mma.sync.m16n8k16 fp16 + cp.async.
//   gates[B,512] = [x|h_] @ [w;wi;wf;wo]^T + bias
//   c = sig(gf)*c_ + sig(gi)*tanh(gz);  h = sig(go)*tanh(c)
//   y = sig(h @ w_out^T + b_out)
// out = [c | h | y] fp32.
// Persistent: 148 CTAs x 512 threads (16 warps: 4m x 4n), 128-row tiles.
// Weights pre-packed (by pack kernels) into fragment-linear fp16 layout so
// each b-frag is a single conflict-free LDS.64.
// ---------------------------------------------------------------------------

#define NTILES 2048
#define NCTAS  148
#define HOFF   33554432L
#define YOFF   67108864L

// SMEM layout (bytes)
#define SA_B     0        // A tile: 128 rows x 256 halfs (swizzled) = 65536
#define SW_B     65536    // weight chunk double buffer: 2 x 32768
#define SWOUT_B  131072   // packed w_out: 32768
#define SH_B     163840   // h tile: 128 rows x 128 halfs (swizzled) = 32768
#define SBIAS_B  196608   // 640 floats = 2560
#define SMEM_TOTAL 199168

// fp16 packed weights, fragment-linear (written by pack kernels each launch)
__device__ __align__(16) __half g_Wg[131072];   // 512x256
__device__ __align__(16) __half g_Wo[16384];    // 128x128

__device__ __forceinline__ uint32_t smem_u32(const void* p) {
    uint32_t a;
    asm("{ .reg .u64 t; cvta.to.shared.u64 t, %1; cvt.u32.u64 %0, t; }" : "=r"(a) : "l"(p));
    return a;
}
__device__ __forceinline__ float tanhap(float x) {
    float y; asm("tanh.approx.f32 %0, %1;" : "=f"(y) : "f"(x)); return y;
}
__device__ __forceinline__ uint32_t packh2(float lo, float hi) {
    uint32_t r; asm("cvt.rn.f16x2.f32 %0, %1, %2;" : "=r"(r) : "f"(hi), "f"(lo));
    return r;
}
__device__ __forceinline__ void cpasync16(uint32_t s, const void* g) {
    asm volatile("cp.async.cg.shared.global [%0], [%1], 16;" :: "r"(s), "l"(g));
}
#define CP_COMMIT() asm volatile("cp.async.commit_group;" ::: "memory")
#define CP_WAIT1()  asm volatile("cp.async.wait_group 1;" ::: "memory")
#define CP_WAIT0()  asm volatile("cp.async.wait_group 0;" ::: "memory")

__device__ __forceinline__ void mma16816(float* d,
                                         uint32_t a0, uint32_t a1, uint32_t a2, uint32_t a3,
                                         uint32_t b0, uint32_t b1) {
    asm volatile(
        "mma.sync.aligned.m16n8k16.row.col.f32.f16.f16.f32 "
        "{%0,%1,%2,%3}, {%4,%5,%6,%7}, {%8,%9}, {%0,%1,%2,%3};"
        : "+f"(d[0]), "+f"(d[1]), "+f"(d[2]), "+f"(d[3])
        : "r"(a0), "r"(a1), "r"(a2), "r"(a3), "r"(b0), "r"(b1));
}

// A-fragment load from swizzled smem (word index = r*rw + (cw ^ 4*(r&7)))
__device__ __forceinline__ void lda(uint32_t* a, const uint32_t* base,
                                    int r, int kf, int lane, int rw) {
    int s = 4 * (r & 7);                 // (r+8)&7 == r&7
    int c0 = kf * 8 + (lane & 3);
    a[0] = base[r * rw + (c0 ^ s)];
    a[1] = base[(r + 8) * rw + (c0 ^ s)];
    a[2] = base[r * rw + ((c0 + 4) ^ s)];
    a[3] = base[(r + 8) * rw + ((c0 + 4) ^ s)];
}

// ---------------------------------------------------------------------------
// Pack kernels: fp32 weights -> fragment-linear fp16.
// Gates layout: [p(2)][c(4)][kk(4)][lnt(32)][lane(32)][reg(2)] 32-bit words,
// where gate col gc = g*128+cc, cc = p*64 + wn*16 + j*8 + n (n=0..7),
// lnt = g*8 + wn*2 + j; k = c*64 + kk*16 + kk16;
// lane = n*4 + ((kk16&7)>>1); reg = kk16>>3; half = k&1.
// ---------------------------------------------------------------------------
__global__ void pack_gates(const float* __restrict__ w, const float* __restrict__ wi,
                           const float* __restrict__ wf, const float* __restrict__ wo) {
    int idx = blockIdx.x * 256 + threadIdx.x;        // 65536 words
    int gc = idx >> 7, k2 = idx & 127, k = k2 * 2;
    int g = gc >> 7, cc = gc & 127;
    const float* src = (g == 0) ? w : (g == 1) ? wi : (g == 2) ? wf : wo;
    float v0 = src[cc * 256 + k];
    float v1 = src[cc * 256 + k + 1];
    int p = cc >> 6, wn = (cc >> 4) & 3, j = (cc >> 3) & 1;
    int lnt = g * 8 + wn * 2 + j;
    int c = k >> 6, kk = (k >> 4) & 3, kk16 = k & 15, reg = kk16 >> 3;
    int lane = ((cc & 7) << 2) | ((kk16 & 7) >> 1);
    int word = ((((p * 4 + c) * 4 + kk) * 32 + lnt) * 32 + lane) * 2 + reg;
    ((uint32_t*)g_Wg)[word] = packh2(v0, v1);
}

// Wout layout: [kf(8)][lnt(16)][lane(32)][reg(2)] words; yc = wn*32+jj*8+n,
// lnt = wn*4 + jj.
__global__ void pack_wout(const float* __restrict__ w_out) {
    int idx = blockIdx.x * 256 + threadIdx.x;        // 8192 words
    int yc = idx >> 6, k2 = idx & 63, k = k2 * 2;
    float v0 = w_out[yc * 128 + k];
    float v1 = w_out[yc * 128 + k + 1];
    int wn = yc >> 5, jj = (yc >> 3) & 3;
    int lnt = wn * 4 + jj;
    int kf = k >> 4, kk16 = k & 15, reg = kk16 >> 3;
    int lane = ((yc & 7) << 2) | ((kk16 & 7) >> 1);
    int word = ((kf * 16 + lnt) * 32 + lane) * 2 + reg;
    ((uint32_t*)g_Wo)[word] = packh2(v0, v1);
}

// ---------------------------------------------------------------------------
// Main persistent kernel
// ---------------------------------------------------------------------------
__global__ void __launch_bounds__(512, 1)
lstm_kernel(const float* __restrict__ c_, const float* __restrict__ h_,
            const float* __restrict__ x,
            const float* __restrict__ b, const float* __restrict__ bi,
            const float* __restrict__ bf, const float* __restrict__ bo,
            const float* __restrict__ b_out, float* __restrict__ out) {
    extern __shared__ char smem[];
    const int tid = threadIdx.x;
    const int wid = tid >> 5;
    const int lane = tid & 31;
    const int wm = wid >> 2;       // m-warp: rows wm*32 .. +32
    const int wn = wid & 3;        // n-warp: c-cols wn*16 .. +16 (per pass half)

    uint32_t* SAw = (uint32_t*)(smem + SA_B);
    uint32_t* SWw = (uint32_t*)(smem + SW_B);
    uint32_t* SOw = (uint32_t*)(smem + SWOUT_B);
    uint32_t* SHw = (uint32_t*)(smem + SH_B);
    float* sb = (float*)(smem + SBIAS_B);

    // one-time: biases + packed wout into smem
    if (tid < 128) {
        sb[tid]       = b[tid];
        sb[128 + tid] = bi[tid];
        sb[256 + tid] = bf[tid];
        sb[384 + tid] = bo[tid];
        sb[512 + tid] = b_out[tid];
    }
#pragma unroll
    for (int i = 0; i < 4; i++) {
        *(uint4*)((char*)SOw + tid * 64 + i * 16) =
            *(const uint4*)((const char*)g_Wo + tid * 64 + i * 16);
    }
    __syncthreads();

    const int rbase = wm * 32 + (lane >> 2);
    const int cpart = (lane & 3) * 2;

    for (int t = blockIdx.x; t < NTILES; t += NCTAS) {
        const long rowbase = (long)t * 128;

        // ---- fill A = [x | h_] fp16, swizzled; rows 128 x 256 halfs ----
        {
            const int r = tid >> 2;
            const int q = tid & 3;
            const float* src = (q < 2) ? x : h_;
            const float* srow = src + (rowbase + r) * 128 + (q & 1) * 64;
            const int s = 4 * (r & 7);
            uint32_t* dst = SAw + r * 128;
#pragma unroll
            for (int i = 0; i < 16; i++) {
                float4 v = *(const float4*)(srow + i * 4);
                int cw = q * 32 + i * 2;
                *(uint2*)(dst + (cw ^ s)) =
                    make_uint2(packh2(v.x, v.y), packh2(v.z, v.w));
            }
        }

        // ---- gates: 2 passes (col halves) x 4 k-chunks, cp.async pipelined ----
        float acc[2][4][2][4];
#pragma unroll
        for (int a = 0; a < 2; a++)
#pragma unroll
            for (int g = 0; g < 4; g++)
#pragma unroll
                for (int j = 0; j < 2; j++)
#pragma unroll
                    for (int q = 0; q < 4; q++) acc[a][g][j][q] = 0.0f;

        // prologue: chunk 0
        {
            uint32_t dsts = smem_u32((char*)SWw + tid * 64);
            const char* srcs = (const char*)g_Wg + tid * 64;
#pragma unroll
            for (int i = 0; i < 4; i++) cpasync16(dsts + i * 16, srcs + i * 16);
            CP_COMMIT();
        }

        for (int ch = 0; ch < 8; ch++) {
            if (ch < 7) {
                uint32_t dsts = smem_u32((char*)SWw + ((ch + 1) & 1) * 32768 + tid * 64);
                const char* srcs = (const char*)g_Wg + (ch + 1) * 32768 + tid * 64;
#pragma unroll
                for (int i = 0; i < 4; i++) cpasync16(dsts + i * 16, srcs + i * 16);
                CP_COMMIT();
                CP_WAIT1();
            } else {
                CP_WAIT0();
            }
            __syncthreads();

            const uint32_t* wb = SWw + (ch & 1) * 8192;
            const int c4 = (ch & 3) * 4;
#pragma unroll
            for (int kk = 0; kk < 4; kk++) {
                const int kf = c4 + kk;
                uint32_t a0[4], a1[4];
                lda(a0, SAw, rbase, kf, lane, 128);
                lda(a1, SAw, rbase + 16, kf, lane, 128);
#pragma unroll
                for (int g = 0; g < 4; g++)
#pragma unroll
                    for (int j = 0; j < 2; j++) {
                        const int lnt = g * 8 + wn * 2 + j;
                        const uint32_t* bp = wb + ((kk * 32 + lnt) * 32 + lane) * 2;
                        uint32_t b0 = bp[0], b1 = bp[1];
                        mma16816(acc[0][g][j], a0[0], a0[1], a0[2], a0[3], b0, b1);
                        mma16816(acc[1][g][j], a1[0], a1[1], a1[2], a1[3], b0, b1);
                    }
            }
            __syncthreads();

            if (ch == 3 || ch == 7) {
                // ---- gates epilogue for pass p = ch>>2 ----
                const int p = ch >> 2;
                const int ccb = p * 64 + wn * 16 + cpart;
#pragma unroll
                for (int mf = 0; mf < 2; mf++)
#pragma unroll
                    for (int rh = 0; rh < 2; rh++)
#pragma unroll
                        for (int j = 0; j < 2; j++) {
                            const int rl = rbase + mf * 16 + rh * 8;
                            const long gr = rowbase + rl;
                            const int cc = ccb + j * 8;
                            float gz0 = acc[mf][0][j][rh * 2]     + sb[cc];
                            float gz1 = acc[mf][0][j][rh * 2 + 1] + sb[cc + 1];
                            float gi0 = acc[mf][1][j][rh * 2]     + sb[128 + cc];
                            float gi1 = acc[mf][1][j][rh * 2 + 1] + sb[128 + cc + 1];
                            float gf0 = acc[mf][2][j][rh * 2]     + sb[256 + cc];
                            float gf1 = acc[mf][2][j][rh * 2 + 1] + sb[256 + cc + 1];
                            float go0 = acc[mf][3][j][rh * 2]     + sb[384 + cc];
                            float go1 = acc[mf][3][j][rh * 2 + 1] + sb[384 + cc + 1];
                            float2 cin = *(const float2*)(c_ + gr * 128 + cc);
                            float z0 = tanhap(gz0), z1 = tanhap(gz1);
                            float si0 = 0.5f * tanhap(0.5f * gi0) + 0.5f;
                            float si1 = 0.5f * tanhap(0.5f * gi1) + 0.5f;
                            float sf0 = 0.5f * tanhap(0.5f * gf0) + 0.5f;
                            float sf1 = 0.5f * tanhap(0.5f * gf1) + 0.5f;
                            float so0 = 0.5f * tanhap(0.5f * go0) + 0.5f;
                            float so1 = 0.5f * tanhap(0.5f * go1) + 0.5f;
                            float c0 = sf0 * cin.x + si0 * z0;
                            float c1 = sf1 * cin.y + si1 * z1;
                            float h0 = so0 * tanhap(c0);
                            float h1 = so1 * tanhap(c1);
                            *(float2*)(out + gr * 128 + cc) = make_float2(c0, c1);
                            *(float2*)(out + HOFF + gr * 128 + cc) = make_float2(h0, h1);
                            const int cw = cc >> 1;
                            SHw[rl * 64 + (cw ^ (4 * (rl & 7)))] = packh2(h0, h1);
                        }
                if (p == 0) {
#pragma unroll
                    for (int a = 0; a < 2; a++)
#pragma unroll
                        for (int g = 0; g < 4; g++)
#pragma unroll
                            for (int j = 0; j < 2; j++)
#pragma unroll
                                for (int q = 0; q < 4; q++) acc[a][g][j][q] = 0.0f;
                }
            }
        }
        __syncthreads();   // h tile complete before y MMA

        // ---- y = sig(h @ wout^T + b_out) ----
        {
            float ay[2][4][4];
#pragma unroll
            for (int a = 0; a < 2; a++)
#pragma unroll
                for (int j = 0; j < 4; j++)
#pragma unroll
                    for (int q = 0; q < 4; q++) ay[a][j][q] = 0.0f;
#pragma unroll
            for (int kf = 0; kf < 8; kf++) {
                uint32_t a0[4], a1[4];
                lda(a0, SHw, rbase, kf, lane, 64);
                lda(a1, SHw, rbase + 16, kf, lane, 64);
#pragma unroll
                for (int jj = 0; jj < 4; jj++) {
                    const uint32_t* bp = SOw + ((kf * 16 + wn * 4 + jj) * 32 + lane) * 2;
                    uint32_t b0 = bp[0], b1 = bp[1];
                    mma16816(ay[0][jj], a0[0], a0[1], a0[2], a0[3], b0, b1);
                    mma16816(ay[1][jj], a1[0], a1[1], a1[2], a1[3], b0, b1);
                }
            }
#pragma unroll
            for (int mf = 0; mf < 2; mf++)
#pragma unroll
                for (int rh = 0; rh < 2; rh++)
#pragma unroll
                    for (int jj = 0; jj < 4; jj++) {
                        const int rl = rbase + mf * 16 + rh * 8;
                        const long gr = rowbase + rl;
                        const int yc = wn * 32 + jj * 8 + cpart;
                        float v0 = ay[mf][jj][rh * 2]     + sb[512 + yc];
                        float v1 = ay[mf][jj][rh * 2 + 1] + sb[512 + yc + 1];
                        float y0 = 0.5f * tanhap(0.5f * v0) + 0.5f;
                        float y1 = 0.5f * tanhap(0.5f * v1) + 0.5f;
                        *(float2*)(out + YOFF + gr * 128 + yc) = make_float2(y0, y1);
                    }
        }
        __syncthreads();   // SH/SA free for next tile
    }
}

extern "C" void kernel_launch(void* const* d_in, const int* in_sizes, int n_in,
                              void* d_out, int out_size) {
    const float* c_    = (const float*)d_in[0];
    const float* h_    = (const float*)d_in[1];
    const float* x     = (const float*)d_in[2];
    const float* w     = (const float*)d_in[3];
    const float* wi    = (const float*)d_in[4];
    const float* wf    = (const float*)d_in[5];
    const float* wo    = (const float*)d_in[6];
    const float* w_out = (const float*)d_in[7];
    const float* b     = (const float*)d_in[8];
    const float* bi    = (const float*)d_in[9];
    const float* bf    = (const float*)d_in[10];
    const float* bo    = (const float*)d_in[11];
    const float* b_out = (const float*)d_in[12];
    float* out = (float*)d_out;

    pack_gates<<<256, 256>>>(w, wi, wf, wo);
    pack_wout<<<32, 256>>>(w_out);
    cudaFuncSetAttribute(lstm_kernel, cudaFuncAttributeMaxDynamicSharedMemorySize, SMEM_TOTAL);
    lstm_kernel<<<NCTAS, 512, SMEM_TOTAL>>>(c_, h_, x, b, bi, bf, bo, b_out, out);
}

// round 5
// speedup vs baseline: 1.0585x; 1.0585x over previous
#include <cuda_runtime.h>
#include <cuda_fp16.h>
#include <cstdint>

// ---------------------------------------------------------------------------
// Fused LSTM cell, B=262144, I=H=C=O=128 (compute_100: mma.sync + cp.async).
// 2 CTAs/SM x 256 threads, 64-row tiles. 8 warps, each owns ALL 64 rows and
// a 8-c-col slice of all 4 gates (m1 x n8 tiling -> minimal B-frag traffic).
// Weights streamed warp-privately (cp.async per-warp slices, no block syncs
// in the mainloop). out = [c | h | y] fp32.
// ---------------------------------------------------------------------------

#define GRID   296
#define NT     4096          // 262144 / 64
#define HOFF   33554432L
#define YOFF   67108864L

// smem (bytes)
#define SA_B 0               // A tile: 64 x 256 half = 32768
#define SW_B 32768           // weight double buffer: 2 x 16384
#define SH_B 65536           // h tile: 64 x 128 half = 16384
#define SB_B 81920           // 640 floats = 2560
#define SMEM_TOTAL 84480

// packed fp16 weights, fragment/warp-slice linear (filled by pack kernels)
__device__ __align__(16) __half g_Wg[131072];   // gates 512x256
__device__ __align__(16) __half g_Wo[16384];    // wout 128x128

__device__ __forceinline__ uint32_t smem_u32(const void* p) {
    uint32_t a;
    asm("{ .reg .u64 t; cvta.to.shared.u64 t, %1; cvt.u32.u64 %0, t; }" : "=r"(a) : "l"(p));
    return a;
}
__device__ __forceinline__ float tanhap(float x) {
    float y; asm("tanh.approx.f32 %0, %1;" : "=f"(y) : "f"(x)); return y;
}
__device__ __forceinline__ uint32_t packh2(float lo, float hi) {
    uint32_t r; asm("cvt.rn.f16x2.f32 %0, %1, %2;" : "=r"(r) : "f"(hi), "f"(lo));
    return r;
}
__device__ __forceinline__ void cpasync16(uint32_t s, const void* g) {
    asm volatile("cp.async.cg.shared.global [%0], [%1], 16;" :: "r"(s), "l"(g));
}
#define CP_COMMIT() asm volatile("cp.async.commit_group;" ::: "memory")
#define CP_WAIT1()  asm volatile("cp.async.wait_group 1;" ::: "memory")
#define CP_WAIT0()  asm volatile("cp.async.wait_group 0;" ::: "memory")

__device__ __forceinline__ void mma16816(float* d,
                                         uint32_t a0, uint32_t a1, uint32_t a2, uint32_t a3,
                                         uint32_t b0, uint32_t b1) {
    asm volatile(
        "mma.sync.aligned.m16n8k16.row.col.f32.f16.f16.f32 "
        "{%0,%1,%2,%3}, {%4,%5,%6,%7}, {%8,%9}, {%0,%1,%2,%3};"
        : "+f"(d[0]), "+f"(d[1]), "+f"(d[2]), "+f"(d[3])
        : "r"(a0), "r"(a1), "r"(a2), "r"(a3), "r"(b0), "r"(b1));
}

// A-fragment load from XOR-swizzled smem (word idx = r*rw + (cw ^ 4*(r&7)))
__device__ __forceinline__ void lda(uint32_t* a, const uint32_t* base,
                                    int r, int kf, int lane, int rw) {
    int s = 4 * (r & 7);
    int c0 = kf * 8 + (lane & 3);
    a[0] = base[r * rw + (c0 ^ s)];
    a[1] = base[(r + 8) * rw + (c0 ^ s)];
    a[2] = base[r * rw + ((c0 + 4) ^ s)];
    a[3] = base[(r + 8) * rw + ((c0 + 4) ^ s)];
}

// ---------------------------------------------------------------------------
// Pack kernels: fp32 weights -> warp-slice-linear fp16 fragments.
// Gates: chunk s = p*8+ch (16 KB, 2 kf). word =
//   ((((p*8+ch)*8 + wn)*8 + kk*4 + g)*32 + lane)*2 + reg
// where gate col gc=g*128+cc, cc = p*64+wn*8+n; k = (ch*2+kk)*16+kk16;
// lane = n*4 + ((kk16>>1)&3); reg = kk16>>3; (k even, k+1 odd packed).
// ---------------------------------------------------------------------------
__global__ void pack_gates(const float* __restrict__ w, const float* __restrict__ wi,
                           const float* __restrict__ wf, const float* __restrict__ wo) {
    int idx = blockIdx.x * 256 + threadIdx.x;        // 65536 words
    int gc = idx >> 7, k = (idx & 127) * 2;
    int g = gc >> 7, cc = gc & 127;
    const float* src = (g == 0) ? w : (g == 1) ? wi : (g == 2) ? wf : wo;
    float v0 = src[cc * 256 + k];
    float v1 = src[cc * 256 + k + 1];
    int p = cc >> 6, wn = (cc >> 3) & 7, n = cc & 7;
    int ch = k >> 5, kk = (k >> 4) & 1, kk16 = k & 15;
    int lane = n * 4 + ((kk16 >> 1) & 3), reg = kk16 >> 3;
    int word = ((((p * 8 + ch) * 8 + wn) * 8 + kk * 4 + g) * 32 + lane) * 2 + reg;
    ((uint32_t*)g_Wg)[word] = packh2(v0, v1);
}

// Wout: 2 chunks of 16 KB (4 kf each). yc = wn*16 + jj*8 + n.
// word = (((ch*8 + wn)*8 + kf4*2 + jj)*32 + lane)*2 + reg
__global__ void pack_wout(const float* __restrict__ w_out) {
    int idx = blockIdx.x * 256 + threadIdx.x;        // 8192 words
    int yc = idx >> 6, k = (idx & 63) * 2;
    float v0 = w_out[yc * 128 + k];
    float v1 = w_out[yc * 128 + k + 1];
    int wn = yc >> 4, jj = (yc >> 3) & 1, n = yc & 7;
    int kf = k >> 4, ch = kf >> 2, kf4 = kf & 3, kk16 = k & 15;
    int lane = n * 4 + ((kk16 >> 1) & 3), reg = kk16 >> 3;
    int word = (((ch * 8 + wn) * 8 + kf4 * 2 + jj) * 32 + lane) * 2 + reg;
    ((uint32_t*)g_Wo)[word] = packh2(v0, v1);
}

// issue one warp-slice (2 KB) of global chunk s into smem double buffer
__device__ __forceinline__ void issue_chunk(int s, uint32_t sw_u32, int wn, int lane) {
    const char* src = (s < 16)
        ? (const char*)g_Wg + (size_t)s * 16384
        : (const char*)g_Wo + (size_t)(s - 16) * 16384;
    src += wn * 2048 + lane * 16;
    uint32_t dst = sw_u32 + (s & 1) * 16384 + wn * 2048 + lane * 16;
#pragma unroll
    for (int i = 0; i < 4; i++) cpasync16(dst + i * 512, src + i * 512);
    CP_COMMIT();
}

// ---------------------------------------------------------------------------
// Main persistent kernel
// ---------------------------------------------------------------------------
__global__ void __launch_bounds__(256, 2)
lstm_kernel(const float* __restrict__ c_, const float* __restrict__ h_,
            const float* __restrict__ x,
            const float* __restrict__ b, const float* __restrict__ bi,
            const float* __restrict__ bf, const float* __restrict__ bo,
            const float* __restrict__ b_out, float* __restrict__ out) {
    extern __shared__ char smem[];
    const int tid = threadIdx.x;
    const int wn = tid >> 5;             // warp 0..7 = n-slice
    const int lane = tid & 31;

    uint32_t* SAw = (uint32_t*)(smem + SA_B);
    uint32_t* SWw = (uint32_t*)(smem + SW_B);
    uint32_t* SHw = (uint32_t*)(smem + SH_B);
    float* sb = (float*)(smem + SB_B);
    const uint32_t sw_u32 = smem_u32(smem + SW_B);

    if (tid < 128) {
        sb[tid]       = b[tid];
        sb[128 + tid] = bi[tid];
        sb[256 + tid] = bf[tid];
        sb[384 + tid] = bo[tid];
        sb[512 + tid] = b_out[tid];
    }
    __syncthreads();

    const int rb0 = lane >> 2;           // fragment base row (0..7)
    const int cpart = (lane & 3) * 2;    // col pair within 8-col n-frag

    for (int t = blockIdx.x; t < NT; t += GRID) {
        const long rowbase = (long)t * 64;

        // prologue: start streaming chunk 0 (warp-private slice)
        issue_chunk(0, sw_u32, wn, lane);

        // ---- fill A = [x | h_] fp16, swizzled; 64 rows x 256 halfs ----
        {
            const int r = tid >> 2;
            const int q = tid & 3;
            const float* src = (q < 2) ? x : h_;
            const float* srow = src + (rowbase + r) * 128 + (q & 1) * 64;
            const int s = 4 * (r & 7);
            uint32_t* dst = SAw + r * 128;
#pragma unroll
            for (int i = 0; i < 16; i++) {
                float4 v = *(const float4*)(srow + i * 4);
                int cw = q * 32 + i * 2;
                *(uint2*)(dst + (cw ^ s)) =
                    make_uint2(packh2(v.x, v.y), packh2(v.z, v.w));
            }
        }
        __syncthreads();   // (a) A ready; prev-tile Wbuf readers already past (c)

        // ================= gates: 2 passes x 8 chunks, warp-paced =========
        for (int p = 0; p < 2; p++) {
            float acc[4][4][4];
#pragma unroll
            for (int mf = 0; mf < 4; mf++)
#pragma unroll
                for (int g = 0; g < 4; g++)
#pragma unroll
                    for (int q = 0; q < 4; q++) acc[mf][g][q] = 0.0f;

            for (int ch = 0; ch < 8; ch++) {
                const int s = p * 8 + ch;
                issue_chunk(s + 1, sw_u32, wn, lane);   // s+1 <= 16
                CP_WAIT1();
                __syncwarp();
                const uint32_t* wb = SWw + (s & 1) * 4096 + wn * 512;
#pragma unroll
                for (int kk = 0; kk < 2; kk++) {
                    const int kf = ch * 2 + kk;
                    uint32_t a[4][4];
#pragma unroll
                    for (int mf = 0; mf < 4; mf++)
                        lda(a[mf], SAw, rb0 + mf * 16, kf, lane, 128);
#pragma unroll
                    for (int g = 0; g < 4; g++) {
                        const uint32_t* bp = wb + (kk * 4 + g) * 64 + lane * 2;
                        uint32_t b0 = bp[0], b1 = bp[1];
#pragma unroll
                        for (int mf = 0; mf < 4; mf++)
                            mma16816(acc[mf][g], a[mf][0], a[mf][1], a[mf][2], a[mf][3], b0, b1);
                    }
                }
            }

            // ---- gates epilogue for pass p (warp-local, no sync) ----
            const int cc0 = p * 64 + wn * 8 + cpart;
#pragma unroll
            for (int mf = 0; mf < 4; mf++)
#pragma unroll
                for (int rh = 0; rh < 2; rh++) {
                    const int rl = rb0 + mf * 16 + rh * 8;
                    const long gr = rowbase + rl;
                    float2 cin = *(const float2*)(c_ + gr * 128 + cc0);
                    float gz0 = acc[mf][0][rh * 2]     + sb[cc0];
                    float gz1 = acc[mf][0][rh * 2 + 1] + sb[cc0 + 1];
                    float gi0 = acc[mf][1][rh * 2]     + sb[128 + cc0];
                    float gi1 = acc[mf][1][rh * 2 + 1] + sb[128 + cc0 + 1];
                    float gf0 = acc[mf][2][rh * 2]     + sb[256 + cc0];
                    float gf1 = acc[mf][2][rh * 2 + 1] + sb[256 + cc0 + 1];
                    float go0 = acc[mf][3][rh * 2]     + sb[384 + cc0];
                    float go1 = acc[mf][3][rh * 2 + 1] + sb[384 + cc0 + 1];
                    float z0 = tanhap(gz0), z1 = tanhap(gz1);
                    float si0 = 0.5f * tanhap(0.5f * gi0) + 0.5f;
                    float si1 = 0.5f * tanhap(0.5f * gi1) + 0.5f;
                    float sf0 = 0.5f * tanhap(0.5f * gf0) + 0.5f;
                    float sf1 = 0.5f * tanhap(0.5f * gf1) + 0.5f;
                    float so0 = 0.5f * tanhap(0.5f * go0) + 0.5f;
                    float so1 = 0.5f * tanhap(0.5f * go1) + 0.5f;
                    float c0 = sf0 * cin.x + si0 * z0;
                    float c1 = sf1 * cin.y + si1 * z1;
                    float h0 = so0 * tanhap(c0);
                    float h1 = so1 * tanhap(c1);
                    *(float2*)(out + gr * 128 + cc0) = make_float2(c0, c1);
                    *(float2*)(out + HOFF + gr * 128 + cc0) = make_float2(h0, h1);
                    SHw[rl * 64 + ((cc0 >> 1) ^ (4 * (rl & 7)))] = packh2(h0, h1);
                }
        }
        __syncthreads();   // (b) h tile complete

        // ================= y = sig(h @ wout^T + b_out) =====================
        {
            float ay[4][2][4];
#pragma unroll
            for (int mf = 0; mf < 4; mf++)
#pragma unroll
                for (int jj = 0; jj < 2; jj++)
#pragma unroll
                    for (int q = 0; q < 4; q++) ay[mf][jj][q] = 0.0f;

            for (int ch = 0; ch < 2; ch++) {
                const int s = 16 + ch;
                if (ch == 0) { issue_chunk(17, sw_u32, wn, lane); CP_WAIT1(); }
                else         { CP_WAIT0(); }
                __syncwarp();
                const uint32_t* wb = SWw + (s & 1) * 4096 + wn * 512;
#pragma unroll
                for (int kf4 = 0; kf4 < 4; kf4++) {
                    const int kf = ch * 4 + kf4;
                    uint32_t a[4][4];
#pragma unroll
                    for (int mf = 0; mf < 4; mf++)
                        lda(a[mf], SHw, rb0 + mf * 16, kf, lane, 64);
#pragma unroll
                    for (int jj = 0; jj < 2; jj++) {
                        const uint32_t* bp = wb + (kf4 * 2 + jj) * 64 + lane * 2;
                        uint32_t b0 = bp[0], b1 = bp[1];
#pragma unroll
                        for (int mf = 0; mf < 4; mf++)
                            mma16816(ay[mf][jj], a[mf][0], a[mf][1], a[mf][2], a[mf][3], b0, b1);
                    }
                }
            }
#pragma unroll
            for (int mf = 0; mf < 4; mf++)
#pragma unroll
                for (int rh = 0; rh < 2; rh++)
#pragma unroll
                    for (int jj = 0; jj < 2; jj++) {
                        const int rl = rb0 + mf * 16 + rh * 8;
                        const long gr = rowbase + rl;
                        const int yc0 = wn * 16 + jj * 8 + cpart;
                        float v0 = ay[mf][jj][rh * 2]     + sb[512 + yc0];
                        float v1 = ay[mf][jj][rh * 2 + 1] + sb[512 + yc0 + 1];
                        float y0 = 0.5f * tanhap(0.5f * v0) + 0.5f;
                        float y1 = 0.5f * tanhap(0.5f * v1) + 0.5f;
                        *(float2*)(out + YOFF + gr * 128 + yc0) = make_float2(y0, y1);
                    }
        }
        __syncthreads();   // (c) SHw/Wbuf free for next tile
    }
}

extern "C" void kernel_launch(void* const* d_in, const int* in_sizes, int n_in,
                              void* d_out, int out_size) {
    const float* c_    = (const float*)d_in[0];
    const float* h_    = (const float*)d_in[1];
    const float* x     = (const float*)d_in[2];
    const float* w     = (const float*)d_in[3];
    const float* wi    = (const float*)d_in[4];
    const float* wf    = (const float*)d_in[5];
    const float* wo    = (const float*)d_in[6];
    const float* w_out = (const float*)d_in[7];
    const float* b     = (const float*)d_in[8];
    const float* bi    = (const float*)d_in[9];
    const float* bf    = (const float*)d_in[10];
    const float* bo    = (const float*)d_in[11];
    const float* b_out = (const float*)d_in[12];
    float* out = (float*)d_out;

    pack_gates<<<256, 256>>>(w, wi, wf, wo);
    pack_wout<<<32, 256>>>(w_out);
    cudaFuncSetAttribute(lstm_kernel, cudaFuncAttributeMaxDynamicSharedMemorySize, SMEM_TOTAL);
    lstm_kernel<<<GRID, 256, SMEM_TOTAL>>>(c_, h_, x, b, bi, bf, bo, b_out, out);
}